// round 1
// baseline (speedup 1.0000x reference)
#include <cuda_runtime.h>
#include <cuda_bf16.h>
#include <cstdint>

// out[b, p*64+m] = w[p,1]*S_b + (w[p,0]-w[p,1])*x[b,m],  S_b = sum_n x[b,n]
// (indices = 1 - eye(64) collapses the einsum to rank-1 + diagonal correction)
//
// One warp per row b. 64 MB read + 512 MB write => HBM-bound, ~80-100 us target.

__global__ __launch_bounds__(256) void perm_closed_kernel(
    const float* __restrict__ x,
    const float* __restrict__ w,
    float* __restrict__ out,
    int B)
{
    const int gtid = blockIdx.x * blockDim.x + threadIdx.x;
    const int row  = gtid >> 5;          // warp id = row b
    const int lane = threadIdx.x & 31;
    if (row >= B) return;

    // Load this lane's float4 of the x row (16 float4 per row; 2 lanes share one)
    const float4* __restrict__ x4 = reinterpret_cast<const float4*>(x) + (size_t)row * 16;
    const float4 xv = x4[lane & 15];

    // Row sum: every element appears exactly twice across the warp -> reduce, halve.
    float partial = (xv.x + xv.y) + (xv.z + xv.w);
    #pragma unroll
    for (int o = 16; o > 0; o >>= 1)
        partial += __shfl_xor_sync(0xffffffffu, partial, o);
    const float S = partial * 0.5f;

    // Output row = 128 float4. Lane l writes float4 f in {l, l+32, l+64, l+96}.
    //   p = f/16 = (lane>>4) + 2k,  m-block = f%16 = lane&15  (matches xv).
    float4* __restrict__ o4 = reinterpret_cast<float4*>(out) + (size_t)row * 128;
    const int p0 = lane >> 4;

    #pragma unroll
    for (int k = 0; k < 4; ++k) {
        const int p = p0 + 2 * k;
        const float w0 = __ldg(w + 2 * p);
        const float w1 = __ldg(w + 2 * p + 1);
        const float a = w1 * S;          // coefficient for the row sum
        const float d = w0 - w1;         // diagonal correction
        float4 r;
        r.x = fmaf(d, xv.x, a);
        r.y = fmaf(d, xv.y, a);
        r.z = fmaf(d, xv.z, a);
        r.w = fmaf(d, xv.w, a);
        o4[lane + 32 * k] = r;
    }
}

extern "C" void kernel_launch(void* const* d_in, const int* in_sizes, int n_in,
                              void* d_out, int out_size)
{
    const float* x = (const float*)d_in[0];   // (B, 64) fp32
    const float* w = (const float*)d_in[1];   // (8, 2)  fp32
    // d_in[2] = indices (64,64) int32 == 1 - eye: structure folded into the math.

    float* out = (float*)d_out;               // (B, 512) fp32
    const int B = in_sizes[0] / 64;

    const int threads = 256;                  // 8 warps = 8 rows per block
    const int rows_per_block = threads / 32;
    const int blocks = (B + rows_per_block - 1) / rows_per_block;
    perm_closed_kernel<<<blocks, threads>>>(x, w, out, B);
}